// round 17
// baseline (speedup 1.0000x reference)
#include <cuda_runtime.h>
#include <cuda_fp16.h>
#include <cstdint>

// ======================= problem constants =======================
static constexpr int MDIM = 16384;   // 8*2048
static constexpr int NDIM = 4096;
static constexpr int KDIM = 4096;

static constexpr int BM = 128;
static constexpr int BN = 128;
static constexpr int BK = 64;            // 64 fp16 = 128B per row
static constexpr int NSTAGE = 3;
static constexpr int NIT = KDIM / BK;    // 64
static constexpr int KC = KDIM / BK;     // 64 k-chunks per tile row

static constexpr int A_BYTES = BM * BK * 2;            // 16384 (one block)
static constexpr int B_BYTES = BN * BK * 2;            // 16384
static constexpr int STAGE_BYTES = A_BYTES + B_BYTES;  // 32768

static constexpr uint32_t SM_BIAS   = 0;     // 128 floats = 512B
static constexpr uint32_t SM_MBAR   = 512;   // full[3] @512..535, empty[3] @536..559
static constexpr uint32_t SM_STAGE0 = 1024;
static constexpr uint32_t SMEM_TOTAL = SM_STAGE0 + NSTAGE * STAGE_BYTES; // 99328

// ======================= scratch (static device globals) =========
// Pre-swizzled tile-contiguous layout: block (tile, kc) is 16 KB contiguous,
// holding rows r=0..127 x 8 chunks of 16B with chunk position sc = c ^ (r&7).
__device__ __align__(256) __half g_xh[(size_t)MDIM * KDIM];  // 128 MB
__device__ __align__(256) __half g_wb[(size_t)NDIM * KDIM];  //  32 MB

// ======================= PTX helpers =============================
__device__ __forceinline__ uint32_t smem_u32(const void* p) {
    uint32_t a;
    asm("{ .reg .u64 t; cvta.to.shared.u64 t, %1; cvt.u32.u64 %0, t; }"
        : "=r"(a) : "l"(p));
    return a;
}

#define MBARRIER_INIT(addr, cnt) \
    asm volatile("mbarrier.init.shared.b64 [%0], %1;" \
                 :: "r"((uint32_t)(addr)), "r"((uint32_t)(cnt)) : "memory")

#define MBARRIER_EXPECT_TX(addr, bytes) \
    asm volatile("mbarrier.arrive.expect_tx.shared.b64 _, [%0], %1;" \
                 :: "r"((uint32_t)(addr)), "r"((uint32_t)(bytes)) : "memory")

#define MBARRIER_ARRIVE(addr) \
    asm volatile("mbarrier.arrive.shared.b64 _, [%0];" \
                 :: "r"((uint32_t)(addr)) : "memory")

#define MBARRIER_WAIT_PARITY(mbar_smem_addr, phase_parity) do { \
    uint32_t _mbar = (uint32_t)(mbar_smem_addr); \
    uint32_t _parity = (uint32_t)(phase_parity); \
    uint32_t _done; \
    asm volatile( \
        "{\n\t" \
        ".reg .pred p;\n\t" \
        "mbarrier.try_wait.parity.acquire.cta.shared::cta.b64 p, [%1], %2;\n\t" \
        "selp.b32 %0, 1, 0, p;\n\t" \
        "}" \
        : "=r"(_done) : "r"(_mbar), "r"(_parity) : "memory"); \
    if (!_done) { \
        asm volatile( \
            "{\n\t" \
            ".reg .pred P1;\n\t" \
            "WAIT_LOOP_%=:\n\t" \
            "mbarrier.try_wait.parity.acquire.cta.shared::cta.b64 P1, [%0], %1, 0x989680;\n\t" \
            "@P1 bra.uni WAIT_DONE_%=;\n\t" \
            "bra.uni WAIT_LOOP_%=;\n\t" \
            "WAIT_DONE_%=:\n\t" \
            "}" \
            :: "r"(_mbar), "r"(_parity) : "memory"); \
    } \
} while (0)

// relaxed: post-wait SMEM writes are async-proxy (bulk) only
#define MBARRIER_WAIT_PARITY_RELAXED(mbar_smem_addr, phase_parity) do { \
    uint32_t _mbar = (uint32_t)(mbar_smem_addr); \
    uint32_t _parity = (uint32_t)(phase_parity); \
    uint32_t _done; \
    asm volatile( \
        "{\n\t" \
        ".reg .pred p;\n\t" \
        "mbarrier.try_wait.parity.relaxed.cta.shared::cta.b64 p, [%1], %2, 0x989680;\n\t" \
        "selp.b32 %0, 1, 0, p;\n\t" \
        "}" \
        : "=r"(_done) : "r"(_mbar), "r"(_parity) : "memory"); \
    if (!_done) { \
        asm volatile( \
            "{\n\t" \
            ".reg .pred P1;\n\t" \
            "WAIT_LOOP_%=:\n\t" \
            "mbarrier.try_wait.parity.relaxed.cta.shared::cta.b64 P1, [%0], %1, 0x989680;\n\t" \
            "@P1 bra.uni WAIT_DONE_%=;\n\t" \
            "bra.uni WAIT_LOOP_%=;\n\t" \
            "WAIT_DONE_%=:\n\t" \
            "}" \
            :: "r"(_mbar), "r"(_parity) : "memory"); \
    } \
} while (0)

__device__ __forceinline__ void bulk_g2s(uint32_t dst_smem, const void* src,
                                         uint32_t bytes, uint32_t mbar) {
    asm volatile(
        "cp.async.bulk.shared::cluster.global.mbarrier::complete_tx::bytes "
        "[%0], [%1], %2, [%3];"
        :: "r"(dst_smem), "l"(src), "r"(bytes), "r"(mbar) : "memory");
}

__device__ __forceinline__ void ldsm_x4(uint32_t& r0, uint32_t& r1,
                                        uint32_t& r2, uint32_t& r3, uint32_t addr) {
    asm volatile("ldmatrix.sync.aligned.m8n8.x4.shared.b16 {%0,%1,%2,%3}, [%4];"
                 : "=r"(r0), "=r"(r1), "=r"(r2), "=r"(r3) : "r"(addr));
}

__device__ __forceinline__ void mma16816(float* c, const uint32_t* a,
                                         const uint32_t* b) {
    asm volatile(
        "mma.sync.aligned.m16n8k16.row.col.f32.f16.f16.f32 "
        "{%0,%1,%2,%3}, {%4,%5,%6,%7}, {%8,%9}, {%0,%1,%2,%3};"
        : "+f"(c[0]), "+f"(c[1]), "+f"(c[2]), "+f"(c[3])
        : "r"(a[0]), "r"(a[1]), "r"(a[2]), "r"(a[3]), "r"(b[0]), "r"(b[1]));
}

// ======================= fused prep kernel =======================
// Writes the pre-swizzled tile-contiguous layout (identical to R16).
static constexpr int XB = 8192;
static constexpr int WB = 4096;

__global__ void __launch_bounds__(256) prep_kernel(const float4* __restrict__ x,
                                                   const float4* __restrict__ w) {
    if (blockIdx.x < XB) {
        const int nchunk = (int)((size_t)MDIM * KDIM / 8);   // 16B chunks
        uint4* o = reinterpret_cast<uint4*>(g_xh);
        int i = blockIdx.x * 256 + threadIdx.x;
        const int st = XB * 256;
        for (; i < nchunk; i += st) {
            int b = i >> 10;
            int wdx = i & 1023;
            int r = wdx >> 3, sc = wdx & 7;
            int cc = sc ^ (r & 7);
            int m = ((b >> 6) << 7) + r;          // tile*128 + r
            int kc = b & 63;
            size_t e4 = ((size_t)m * KDIM + (kc << 6) + (cc << 3)) >> 2;
            float4 v0 = x[e4];
            float4 v1 = x[e4 + 1];
            union { __half2 h; uint32_t u; } p0, p1, p2, p3;
            p0.h = __floats2half2_rn(v0.x, v0.y);
            p1.h = __floats2half2_rn(v0.z, v0.w);
            p2.h = __floats2half2_rn(v1.x, v1.y);
            p3.h = __floats2half2_rn(v1.z, v1.w);
            o[i] = make_uint4(p0.u, p1.u, p2.u, p3.u);
        }
    } else {
        const int nchunk = (int)((size_t)NDIM * KDIM / 8);
        uint4* o = reinterpret_cast<uint4*>(g_wb);
        int i = (blockIdx.x - XB) * 256 + threadIdx.x;
        const int st = WB * 256;
        for (; i < nchunk; i += st) {
            int b = i >> 10;
            int wdx = i & 1023;
            int r = wdx >> 3, sc = wdx & 7;
            int cc = sc ^ (r & 7);
            int n = ((b >> 6) << 7) + r;
            int kc = b & 63;
            size_t e4 = ((size_t)n * KDIM + (kc << 6) + (cc << 3)) >> 2;
            float4 v0 = w[e4];
            float4 v1 = w[e4 + 1];
            union { __half2 h; uint32_t u; } p0, p1, p2, p3;
            p0.h = __floats2half2_rn(v0.x >= 0.f ? 1.f : -1.f, v0.y >= 0.f ? 1.f : -1.f);
            p1.h = __floats2half2_rn(v0.z >= 0.f ? 1.f : -1.f, v0.w >= 0.f ? 1.f : -1.f);
            p2.h = __floats2half2_rn(v1.x >= 0.f ? 1.f : -1.f, v1.y >= 0.f ? 1.f : -1.f);
            p3.h = __floats2half2_rn(v1.z >= 0.f ? 1.f : -1.f, v1.w >= 0.f ? 1.f : -1.f);
            o[i] = make_uint4(p0.u, p1.u, p2.u, p3.u);
        }
    }
}

// ======================= GEMM kernel =============================
// 256 threads = 8 warps, warp layout 2 (M) x 4 (N), warp tile 64x32.
// 2 CTAs/SM. R16 + (a) full/empty mbarrier pipeline, no per-iter
// __syncthreads (warps run up to 2 stages ahead); (b) XOR-folded
// LDSM addressing.
__global__ void __launch_bounds__(256, 2) gemm_kernel(const float* __restrict__ bias,
                                                      float* __restrict__ out) {
    extern __shared__ char smem[];
    const uint32_t smem_base = smem_u32(smem);
    const int tid = threadIdx.x;
    const int wid = tid >> 5;
    const int lane = tid & 31;

    // grouped rasterization for L2 locality
    constexpr int NTN = NDIM / BN;  // 32
    constexpr int GM = 8;
    int pid = blockIdx.x;
    int group = pid / (GM * NTN);
    int rem = pid % (GM * NTN);
    int pm = group * GM + (rem % GM);
    int pn = rem / GM;
    const int m0 = pm * BM;
    const int n0 = pn * BN;

    if (tid < BN) reinterpret_cast<float*>(smem + SM_BIAS)[tid] = bias[n0 + tid];

    // block sources: block (tile, kc) at byte offset (tile*KC + kc)*16384
    const char* srcA = reinterpret_cast<const char*>(g_xh) + (size_t)pm * KC * A_BYTES;
    const char* srcB = reinterpret_cast<const char*>(g_wb) + (size_t)pn * KC * B_BYTES;

    const uint32_t mbF = smem_base + SM_MBAR;        // full[s]  = mbF + 8s
    const uint32_t mbE = smem_base + SM_MBAR + 24;   // empty[s] = mbE + 8s

    if (tid == 0) {
        #pragma unroll
        for (int s = 0; s < NSTAGE; s++) {
            MBARRIER_INIT(mbF + 8 * s, 1);
            MBARRIER_INIT(mbE + 8 * s, 256);
        }
    }
    __syncthreads();   // mbarrier init + bias visible to all

    // prologue: arm stages 0,1 with k-chunks 0,1
    if (tid == 0) {
        #pragma unroll
        for (int j = 0; j < NSTAGE - 1; j++) {
            uint32_t mb = mbF + 8 * j;
            uint32_t dst = smem_base + SM_STAGE0 + (uint32_t)j * STAGE_BYTES;
            MBARRIER_EXPECT_TX(mb, STAGE_BYTES);
            bulk_g2s(dst, srcA + (size_t)j * A_BYTES, A_BYTES, mb);
            bulk_g2s(dst + A_BYTES, srcB + (size_t)j * B_BYTES, B_BYTES, mb);
        }
    }

    // ---- per-warp fragment addressing (XOR-folded) ----
    const int warpM = wid & 1;          // 0..1
    const int warpN = wid >> 1;         // 0..3
    const int l16 = lane & 15;
    const uint32_t colb = (uint32_t)((lane >> 4) * 16);

    // off = row*128 + (colb ^ ((row&7)*16)); LDSM addr = (stage + off) ^ (ks*32)
    uint32_t offA2[4];
    #pragma unroll
    for (int mf = 0; mf < 4; mf++) {
        int row = warpM * 64 + mf * 16 + l16;
        offA2[mf] = (uint32_t)(row * 128) + (colb ^ (uint32_t)((row & 7) * 16));
    }
    uint32_t offB2[2];
    #pragma unroll
    for (int nh = 0; nh < 2; nh++) {
        int row = warpN * 32 + nh * 16 + l16;
        offB2[nh] = (uint32_t)(row * 128) + (colb ^ (uint32_t)((row & 7) * 16));
    }

    float acc[4][4][4];
    #pragma unroll
    for (int mf = 0; mf < 4; mf++)
        #pragma unroll
        for (int nf = 0; nf < 4; nf++)
            #pragma unroll
            for (int k = 0; k < 4; k++) acc[mf][nf][k] = 0.f;

    // one ks block: 6 LDSM.x4 (base^kx) + 16 HMMA
    auto compute_ks = [&](const uint32_t* aA, const uint32_t* aB, int ks) {
        const uint32_t kx = (uint32_t)(ks * 32);
        uint32_t a[4][4];
        #pragma unroll
        for (int mf = 0; mf < 4; mf++)
            ldsm_x4(a[mf][0], a[mf][1], a[mf][2], a[mf][3], aA[mf] ^ kx);
        uint32_t br[2][4];
        #pragma unroll
        for (int nh = 0; nh < 2; nh++)
            ldsm_x4(br[nh][0], br[nh][1], br[nh][2], br[nh][3], aB[nh] ^ kx);
        #pragma unroll
        for (int mf = 0; mf < 4; mf++) {
            #pragma unroll
            for (int nf = 0; nf < 4; nf++) {
                uint32_t b2[2];
                b2[0] = br[nf >> 1][nf & 1];
                b2[1] = br[nf >> 1][(nf & 1) + 2];
                mma16816(acc[mf][nf], a[mf], b2);
            }
        }
    };

    // ---- main loop: no __syncthreads; full/empty mbarrier pipeline ----
    const int ks0 = wid & 3;    // warp-dependent phase
    for (int it = 0; it < NIT; ++it) {
        // producer: arm stage for chunk j = it+2 (reuses stage of iter it-1)
        int j = it + NSTAGE - 1;
        if (tid == 0 && j < NIT) {
            int s = j % NSTAGE;
            if (j >= NSTAGE) {
                // wait all 256 consumer arrivals from iter j-3 (= it-1)
                MBARRIER_WAIT_PARITY_RELAXED(mbE + 8 * s, (uint32_t)(((it - 1) / 3) & 1));
            }
            uint32_t mb = mbF + 8 * s;
            uint32_t dst = smem_base + SM_STAGE0 + (uint32_t)s * STAGE_BYTES;
            MBARRIER_EXPECT_TX(mb, STAGE_BYTES);
            bulk_g2s(dst, srcA + (size_t)j * A_BYTES, A_BYTES, mb);
            bulk_g2s(dst + A_BYTES, srcB + (size_t)j * B_BYTES, B_BYTES, mb);
        }

        int cur = it % NSTAGE;
        MBARRIER_WAIT_PARITY(mbF + 8 * cur, (uint32_t)((it / 3) & 1));

        uint32_t sA = smem_base + SM_STAGE0 + (uint32_t)cur * STAGE_BYTES;
        uint32_t sB = sA + A_BYTES;
        uint32_t aA[4], aB[2];
        #pragma unroll
        for (int mf = 0; mf < 4; mf++) aA[mf] = sA + offA2[mf];
        #pragma unroll
        for (int nh = 0; nh < 2; nh++) aB[nh] = sB + offB2[nh];

        compute_ks(aA, aB, ks0);
        #pragma unroll
        for (int kk = 1; kk < 4; kk++)
            compute_ks(aA, aB, (ks0 + kk) & 3);

        MBARRIER_ARRIVE(mbE + 8 * cur);   // this thread done reading stage cur
    }

    // ---- epilogue (unchanged; bias visible since pre-init sync) ----
    const float* sb = reinterpret_cast<const float*>(smem + SM_BIAS);
    const int groupid = lane >> 2;
    const int tid4 = lane & 3;
    #pragma unroll
    for (int mf = 0; mf < 4; mf++) {
        int m = m0 + warpM * 64 + mf * 16 + groupid;
        #pragma unroll
        for (int nf = 0; nf < 4; nf++) {
            int nl = warpN * 32 + nf * 8 + tid4 * 2;
            int n = n0 + nl;
            float2 v0;
            v0.x = acc[mf][nf][0] + sb[nl];
            v0.y = acc[mf][nf][1] + sb[nl + 1];
            *reinterpret_cast<float2*>(out + (size_t)m * NDIM + n) = v0;
            float2 v1;
            v1.x = acc[mf][nf][2] + sb[nl];
            v1.y = acc[mf][nf][3] + sb[nl + 1];
            *reinterpret_cast<float2*>(out + (size_t)(m + 8) * NDIM + n) = v1;
        }
    }
}

// ======================= launch ==================================
extern "C" void kernel_launch(void* const* d_in, const int* in_sizes, int n_in,
                              void* d_out, int out_size) {
    (void)in_sizes; (void)n_in; (void)out_size;
    const float* x    = (const float*)d_in[0];
    const float* w    = (const float*)d_in[1];
    const float* bias = (const float*)d_in[2];
    float* out = (float*)d_out;

    prep_kernel<<<XB + WB, 256>>>((const float4*)x, (const float4*)w);

    cudaFuncSetAttribute(gemm_kernel, cudaFuncAttributeMaxDynamicSharedMemorySize,
                         (int)SMEM_TOTAL);
    int grid = (MDIM / BM) * (NDIM / BN);  // 4096
    gemm_kernel<<<grid, 256, SMEM_TOTAL>>>(bias, out);
}